// round 10
// baseline (speedup 1.0000x reference)
#include <cuda_runtime.h>
#include <cuda_bf16.h>
#include <math.h>
#include <stdint.h>

#define TT 4096
#define KTOT (64*4096)   /* 262144 */
#define FD 512

// ---------------- scratch (static device globals) ----------------
__device__ __nv_bfloat16 g_Ah[(size_t)320 * KTOT];
__device__ __nv_bfloat16 g_Al[(size_t)320 * KTOT];
__device__ __nv_bfloat16 g_Wh[(size_t)KTOT * FD];
__device__ __nv_bfloat16 g_Wl[(size_t)KTOT * FD];
__device__ float g_feats[320 * FD];
__device__ float g_norms[320];
__device__ float g_cons;
__device__ float g_contr;

// ---------------- PTX helpers (baseline ISA only) ----------------
__device__ __forceinline__ uint32_t smem_to_u32(const void* p) {
    uint32_t a;
    asm("{ .reg .u64 t; cvta.to.shared.u64 t, %1; cvt.u32.u64 %0, t; }" : "=r"(a) : "l"(p));
    return a;
}
__device__ __forceinline__ void ldsm_x4(uint32_t* r, uint32_t addr) {
    asm volatile("ldmatrix.sync.aligned.m8n8.x4.shared.b16 {%0,%1,%2,%3}, [%4];"
        : "=r"(r[0]), "=r"(r[1]), "=r"(r[2]), "=r"(r[3]) : "r"(addr));
}
__device__ __forceinline__ void ldsm_x4_trans(uint32_t* r, uint32_t addr) {
    asm volatile("ldmatrix.sync.aligned.m8n8.x4.trans.shared.b16 {%0,%1,%2,%3}, [%4];"
        : "=r"(r[0]), "=r"(r[1]), "=r"(r[2]), "=r"(r[3]) : "r"(addr));
}
__device__ __forceinline__ void mma_bf16(float* c, const uint32_t* a, const uint32_t* b) {
    asm volatile("mma.sync.aligned.m16n8k16.row.col.f32.bf16.bf16.f32 "
        "{%0,%1,%2,%3}, {%4,%5,%6,%7}, {%8,%9}, {%0,%1,%2,%3};"
        : "+f"(c[0]), "+f"(c[1]), "+f"(c[2]), "+f"(c[3])
        : "r"(a[0]), "r"(a[1]), "r"(a[2]), "r"(a[3]), "r"(b[0]), "r"(b[1]));
}
__device__ __forceinline__ void cp_async16(uint32_t smem, const void* g) {
    asm volatile("cp.async.cg.shared.global [%0], [%1], 16;" :: "r"(smem), "l"(g));
}
#define CP_COMMIT() asm volatile("cp.async.commit_group;" ::: "memory")
#define CP_WAIT1()  asm volatile("cp.async.wait_group 1;" ::: "memory")
#define CP_WAIT0()  asm volatile("cp.async.wait_group 0;" ::: "memory")

// ---------------- block reductions ----------------
__device__ __forceinline__ float blockReduceSum(float v, float* red) {
    int lane = threadIdx.x & 31, w = threadIdx.x >> 5;
    int nw = blockDim.x >> 5;
    #pragma unroll
    for (int o = 16; o; o >>= 1) v += __shfl_down_sync(0xffffffffu, v, o);
    if (lane == 0) red[w] = v;
    __syncthreads();
    if (w == 0) {
        float r = (lane < nw) ? red[lane] : 0.0f;
        #pragma unroll
        for (int o = 8; o; o >>= 1) r += __shfl_down_sync(0xffffffffu, r, o);
        if (lane == 0) red[0] = r;
    }
    __syncthreads();
    float out = red[0];
    __syncthreads();
    return out;
}
__device__ __forceinline__ float blockReduceMax(float v, float* red) {
    int lane = threadIdx.x & 31, w = threadIdx.x >> 5;
    int nw = blockDim.x >> 5;
    #pragma unroll
    for (int o = 16; o; o >>= 1) v = fmaxf(v, __shfl_down_sync(0xffffffffu, v, o));
    if (lane == 0) red[w] = v;
    __syncthreads();
    if (w == 0) {
        float r = (lane < nw) ? red[lane] : -3.4e38f;
        #pragma unroll
        for (int o = 8; o; o >>= 1) r = fmaxf(r, __shfl_down_sync(0xffffffffu, r, o));
        if (lane == 0) red[0] = r;
    }
    __syncthreads();
    float out = red[0];
    __syncthreads();
    return out;
}

// ---------------- complex / masks / skew ----------------
__device__ __forceinline__ float2 f2add(float2 a, float2 b) { return make_float2(a.x + b.x, a.y + b.y); }
__device__ __forceinline__ float2 f2sub(float2 a, float2 b) { return make_float2(a.x - b.x, a.y - b.y); }
__device__ __forceinline__ float2 cmul(float2 a, float2 b) {
    return make_float2(a.x*b.x - a.y*b.y, a.x*b.y + a.y*b.x);
}
__device__ __forceinline__ float2 cmulc(float2 a, float2 b) {   // conj(a)*b
    return make_float2(a.x*b.x + a.y*b.y, a.x*b.y - a.y*b.x);
}
// folded mask for compressed view (level 0.5): (keep(k)+keep((N-k)%N))/2
__device__ __forceinline__ float m0fold(int k) {
    return (k == 0) ? 1.0f : ((k == 2048) ? 0.0f : 0.5f);
}
// folded fmask: (fm(k)+fm((4096-k)&4095))/2
__device__ __forceinline__ float fmfold(int k, int fs) {
    float f1 = (k >= fs && k < fs + 409) ? 0.1f : 1.0f;
    int k2 = (4096 - k) & 4095;
    float f2 = (k2 >= fs && k2 < fs + 409) ? 0.1f : 1.0f;
    return 0.5f * (f1 + f2);
}
// combined view mask (level 0.25 real-fold g) * fmask — validated since R1 (takes .x)
__device__ __forceinline__ float mask2(int k, int fs) {
    float fm = (k >= fs && k < fs + 409) ? 0.1f : 1.0f;
    float g = (k == 0) ? 1.0f : ((k <= 1024) ? 0.5f : ((k < 3072) ? 1.0f : 0.5f));
    return g * fm;
}
__device__ __forceinline__ int skw3(int g) { return g + (g >> 3); }
#define PLANE3 4608   /* float2 slots per skewed 4096-plane */

// ---------------- radix-8 butterfly ----------------
template<int FWD>
__device__ __forceinline__ void dft8(const float2* e, float2* y) {
    float2 a02s = f2add(e[0], e[4]), a02d = f2sub(e[0], e[4]);
    float2 a13s = f2add(e[2], e[6]), a13d = f2sub(e[2], e[6]);
    float2 A0 = f2add(a02s, a13s), A2 = f2sub(a02s, a13s);
    float2 A1, A3;
    if (FWD) {
        A1 = make_float2(a02d.x + a13d.y, a02d.y - a13d.x);
        A3 = make_float2(a02d.x - a13d.y, a02d.y + a13d.x);
    } else {
        A1 = make_float2(a02d.x - a13d.y, a02d.y + a13d.x);
        A3 = make_float2(a02d.x + a13d.y, a02d.y - a13d.x);
    }
    float2 b02s = f2add(e[1], e[5]), b02d = f2sub(e[1], e[5]);
    float2 b13s = f2add(e[3], e[7]), b13d = f2sub(e[3], e[7]);
    float2 B0 = f2add(b02s, b13s), B2 = f2sub(b02s, b13s);
    float2 B1, B3;
    if (FWD) {
        B1 = make_float2(b02d.x + b13d.y, b02d.y - b13d.x);
        B3 = make_float2(b02d.x - b13d.y, b02d.y + b13d.x);
    } else {
        B1 = make_float2(b02d.x - b13d.y, b02d.y + b13d.x);
        B3 = make_float2(b02d.x + b13d.y, b02d.y - b13d.x);
    }
    const float c = 0.7071067811865476f;
    float2 w1, w2, w3;
    if (FWD) {
        w1 = make_float2(c * (B1.x + B1.y), c * (B1.y - B1.x));
        w2 = make_float2(B2.y, -B2.x);
        w3 = make_float2(c * (B3.y - B3.x), -c * (B3.x + B3.y));
    } else {
        w1 = make_float2(c * (B1.x - B1.y), c * (B1.y + B1.x));
        w2 = make_float2(-B2.y, B2.x);
        w3 = make_float2(-c * (B3.x + B3.y), c * (B3.x - B3.y));
    }
    y[0] = f2add(A0, B0); y[4] = f2sub(A0, B0);
    y[1] = f2add(A1, w1); y[5] = f2sub(A1, w1);
    y[2] = f2add(A2, w2); y[6] = f2sub(A2, w2);
    y[3] = f2add(A3, w3); y[7] = f2sub(A3, w3);
}

// 3 radix-8 smem stages (m = 8, 64, 512). src B0; result in B1.
template<int FWD>
__device__ float2* r8_stages(const float2* __restrict__ tw, float2* B0, float2* B1, int tid) {
    float2 *src = B0, *dst = B1;
    #pragma unroll 1
    for (int s3 = 3; s3 <= 9; s3 += 3) {
        const int m = 1 << s3;
        __syncthreads();
        const int jm = (tid >> s3) << s3;
        float2 e[8], y[8];
        #pragma unroll
        for (int q = 0; q < 8; q++) e[q] = src[skw3(tid + 512 * q)];
        dft8<FWD>(e, y);
        const int base = tid + 7 * jm;
        dst[skw3(base)] = y[0];
        #pragma unroll
        for (int p = 1; p < 8; p++) {
            float2 w = tw[p * jm];
            dst[skw3(base + p * m)] = FWD ? cmul(w, y[p]) : cmulc(w, y[p]);
        }
        float2* t = src; src = dst; dst = t;
    }
    __syncthreads();
    return src;   // == B1
}

// generic inverse pass from register spectrum e[] (already masked/packed)
__device__ float2* inv_core(const float2* __restrict__ tw, float2* e,
                            float2* B0, float2* B1, int tid) {
    float2 y[8];
    dft8<0>(e, y);
    const int base = 8 * tid;
    B0[skw3(base)] = y[0];
    #pragma unroll
    for (int p = 1; p < 8; p++)
        B0[skw3(base + p)] = cmulc(tw[p * tid], y[p]);
    return r8_stages<0>(tw, B0, B1, tid);
}

// ---------------- kernel 0: init ----------------
__global__ void init_kernel(const float* __restrict__ b) {
    int i = blockIdx.x * blockDim.x + threadIdx.x;
    if (i < 320 * FD) g_feats[i] = b[i & 511];
    if (i == 0) { g_cons = 0.0f; g_contr = 0.0f; }
}

// ---------------- views helpers ----------------
__device__ __forceinline__ void store_hl8(size_t idx, const float* v) {
    __align__(16) __nv_bfloat16 hi[8], lo[8];
    #pragma unroll
    for (int q = 0; q < 8; q++) {
        __nv_bfloat16 h = __float2bfloat16_rn(v[q]);
        hi[q] = h;
        lo[q] = __float2bfloat16_rn(v[q] - __bfloat162float(h));
    }
    *(float4*)(g_Ah + idx) = *(float4*)hi;
    *(float4*)(g_Al + idx) = *(float4*)lo;
}
__device__ __forceinline__ void ldg8(float* v, const float* g) {
    float4 u0 = *(const float4*)g;
    float4 u1 = *(const float4*)(g + 4);
    v[0] = u0.x; v[1] = u0.y; v[2] = u0.z; v[3] = u0.w;
    v[4] = u1.x; v[5] = u1.y; v[6] = u1.z; v[7] = u1.w;
}

// ---------------- kernel 1: fused views (radix-8 FFT, packed inverse) + W split ----------------
__global__ void __launch_bounds__(512, 2)
views_kernel(const float* __restrict__ x, const float* __restrict__ W,
             const float* __restrict__ nz1, const float* __restrict__ nz2,
             const int* __restrict__ pfs, const int* __restrict__ pts) {
    const int bx = blockIdx.x;
    const int grp = bx / 9, rr9 = bx % 9;
    const int tid = threadIdx.x;

    if (rr9 == 0) {
        // ---- W hi/lo split slice ----
        size_t base = (size_t)grp * 262144 + (size_t)tid * 8;
        #pragma unroll 1
        for (int j = 0; j < 64; j++) {
            size_t i = base + (size_t)j * 4096;
            float vv[8];
            ldg8(vv, W + i);
            __align__(16) __nv_bfloat16 hi[8], lo[8];
            #pragma unroll
            for (int q = 0; q < 8; q++) {
                __nv_bfloat16 h = __float2bfloat16_rn(vv[q]);
                hi[q] = h;
                lo[q] = __float2bfloat16_rn(vv[q] - __bfloat162float(h));
            }
            *(float4*)(g_Wh + i) = *(float4*)hi;
            *(float4*)(g_Wl + i) = *(float4*)lo;
        }
        return;
    }

    extern __shared__ char smraw[];
    float2* tw = (float2*)smraw;                       // 4096 float2 = 32768 B
    float2* B0 = (float2*)(smraw + 32768);             // PLANE3 float2
    float2* B1 = B0 + PLANE3;
    __shared__ float red[32];

    const int row = grp * 8 + (rr9 - 1);               // 0..4095
    const int bi = row >> 6, ci = row & 63;
    const int fs = *pfs, ts = *pts;
    const size_t xbase = (size_t)row * TT;

    const size_t a0 = (size_t)(0*64 + bi) * KTOT + (size_t)ci * TT;
    const size_t a1 = (size_t)(1*64 + bi) * KTOT + (size_t)ci * TT;
    const size_t a2 = (size_t)(2*64 + bi) * KTOT + (size_t)ci * TT;
    const size_t a3 = (size_t)(3*64 + bi) * KTOT + (size_t)ci * TT;
    const size_t a4 = (size_t)(4*64 + bi) * KTOT + (size_t)ci * TT;

    const int tc = 8 * tid;   // contiguous I/O base

    // twiddles
    #pragma unroll
    for (int j = 0; j < 8; j++) {
        int k = tid + 512 * j;
        float s, c;
        sincospif(-(float)k * (1.0f / 2048.0f), &s, &c);
        tw[k] = make_float2(c, s);
    }

    // contiguous x load; view0; std stats; stash into smem for layout change
    float x8[8];
    ldg8(x8, x + xbase + tc);
    store_hl8(a0 + tc, x8);
    float ls = 0.0f, lq = 0.0f;
    #pragma unroll
    for (int j = 0; j < 8; j++) { ls += x8[j]; lq += x8[j] * x8[j]; }
    {
        float* xs = (float*)B0;
        #pragma unroll
        for (int j = 0; j < 8; j++) xs[tc + j] = x8[j];
    }
    float s1 = blockReduceSum(ls, red);    // internal barriers make xs/tw visible
    float q1 = blockReduceSum(lq, red);
    float std1 = sqrtf(fmaxf(0.0f, (q1 - s1 * s1 * (1.0f / 4096.0f)) * (1.0f / 4095.0f)));

    // noisy view (contiguous)
    {
        float n8[8], o8[8];
        ldg8(n8, nz1 + xbase + tc);
        #pragma unroll
        for (int j = 0; j < 8; j++) o8[j] = x8[j] + n8[j] * (0.02f * std1);
        store_hl8(a3 + tc, o8);
    }

    // pick up x in FFT register layout
    float xv[8];
    {
        const float* xs = (const float*)B0;
        #pragma unroll
        for (int j = 0; j < 8; j++) xv[j] = xs[tid + 512 * j];
    }
    __syncthreads();   // strided reads done before stage0 overwrites B0

    // forward stage 0 from registers (real input)
    {
        float2 e[8], y[8];
        #pragma unroll
        for (int q = 0; q < 8; q++) e[q] = make_float2(xv[q], 0.0f);
        dft8<1>(e, y);
        const int base = 8 * tid;
        B0[skw3(base)] = y[0];
        #pragma unroll
        for (int p = 1; p < 8; p++)
            B0[skw3(base + p)] = cmul(tw[p * tid], y[p]);
    }
    float2* Xp = r8_stages<1>(tw, B0, B1, tid);   // X in B1

    float2 Xr[8];
    #pragma unroll
    for (int j = 0; j < 8; j++) Xr[j] = Xp[skw3(tid + 512 * j)];

    // ---- packed pass: compressed (Re) + distorted (Im) in one inverse FFT ----
    {
        __syncthreads();
        float2 e[8];
        #pragma unroll
        for (int q = 0; q < 8; q++) {
            int k = tid + 512 * q;
            float ma = m0fold(k);
            float mb = fmfold(k, fs);
            // (ma + i*mb) * X
            e[q] = make_float2(ma * Xr[q].x - mb * Xr[q].y,
                               ma * Xr[q].y + mb * Xr[q].x);
        }
        float2* r = inv_core(tw, e, B0, B1, tid);
        float oc[8], od[8];
        #pragma unroll
        for (int j = 0; j < 8; j++) {
            int t = tc + j;
            float2 v = r[skw3(t)];
            oc[j] = v.x * (1.0f / 4096.0f);
            float tm = (t >= ts && t < ts + 204) ? 0.1f : 1.0f;
            od[j] = tm * v.y * (1.0f / 4096.0f);
        }
        store_hl8(a1 + tc, oc);
        store_hl8(a2 + tc, od);
    }

    // ---- pass 2: combined (mask2, take real part — validated path) ----
    {
        __syncthreads();
        float2 e[8];
        #pragma unroll
        for (int q = 0; q < 8; q++) {
            float m = mask2(tid + 512 * q, fs);
            e[q] = make_float2(Xr[q].x * m, Xr[q].y * m);
        }
        float2* r = inv_core(tw, e, B0, B1, tid);
        float vv[8];
        float ls2 = 0.0f, lq2 = 0.0f;
        #pragma unroll
        for (int j = 0; j < 8; j++) {
            int t = tc + j;
            float tm = (t >= ts && t < ts + 204) ? 0.1f : 1.0f;
            float v = tm * r[skw3(t)].x * (1.0f / 4096.0f);
            vv[j] = v;
            ls2 += v; lq2 += v * v;
        }
        float s2 = blockReduceSum(ls2, red);
        float q2 = blockReduceSum(lq2, red);
        float std2 = sqrtf(fmaxf(0.0f, (q2 - s2 * s2 * (1.0f / 4096.0f)) * (1.0f / 4095.0f)));
        float n8[8], o8[8];
        ldg8(n8, nz2 + xbase + tc);
        #pragma unroll
        for (int j = 0; j < 8; j++) o8[j] = vv[j] + n8[j] * (0.02f * std2);
        store_hl8(a4 + tc, o8);
    }
}

// ---------------- kernel 2: 3-stage async mma.sync bf16-split GEMM ----------------
// occ 2 (reg budget 255): all fragments for both kt loaded before the mma block.
#define STG 24576
#define GEMM_SMEM (3 * STG)   /* 73728 */
#define KSPL 14

__global__ void __launch_bounds__(128, 2) gemm_kernel() {
    extern __shared__ char smbuf[];
    const uint32_t sb = smem_to_u32(smbuf);

    const int tid = threadIdx.x;
    const int warp = tid >> 5, lane = tid & 31;
    const int m0 = blockIdx.y * 64;
    const int n0 = blockIdx.x * 128;
    const int z = blockIdx.z;
    // 8192 chunks of 32 over 14 splits: 585 each, first 2 get +1
    const int start_chunk = 585 * z + (z < 2 ? z : 2);
    const int nchunks = 585 + (z < 2 ? 1 : 0);

    const int wm = warp >> 1;
    const int wn = warp & 1;

    float acc[2][8][4];
    #pragma unroll
    for (int a = 0; a < 2; a++)
        #pragma unroll
        for (int b = 0; b < 8; b++)
            #pragma unroll
            for (int c = 0; c < 4; c++) acc[a][b][c] = 0.0f;

    const __nv_bfloat16* srcA[4];
    uint32_t dstA[4];
    #pragma unroll
    for (int i = 0; i < 2; i++) {
        int f = tid + 128 * i;
        int m = f >> 2, kc = f & 3;
        uint32_t rel = (uint32_t)(m * 64 + (((kc + (m >> 1)) & 3) << 4));
        size_t src = (size_t)(m0 + m) * KTOT + (size_t)start_chunk * 32 + kc * 8;
        dstA[i] = rel;            srcA[i] = g_Ah + src;
        dstA[i + 2] = rel + 4096; srcA[i + 2] = g_Al + src;
    }
    const __nv_bfloat16* srcW[8];
    uint32_t dstW[8];
    #pragma unroll
    for (int i = 0; i < 4; i++) {
        int f = tid + 128 * i;
        int k = f >> 4, nc = f & 15;
        uint32_t rel = (uint32_t)(8192 + k * 256 + (((nc ^ (k & 7)) & 15) << 4));
        size_t src = ((size_t)start_chunk * 32 + k) * 512 + n0 + nc * 8;
        dstW[i] = rel;            srcW[i] = g_Wh + src;
        dstW[i + 4] = rel + 8192; srcW[i + 4] = g_Wl + src;
    }

    uint32_t a_ld[2][2];
    {
        int tile = lane >> 3, r = lane & 7;
        #pragma unroll
        for (int mt = 0; mt < 2; mt++)
            #pragma unroll
            for (int kt = 0; kt < 2; kt++) {
                int mm = wm * 32 + mt * 16 + (tile & 1) * 8 + r;
                int kb = kt * 2 + (tile >> 1);
                a_ld[mt][kt] = (uint32_t)(mm * 64 + (((kb + (mm >> 1)) & 3) << 4));
            }
    }
    uint32_t b_ld4[4][2];
    {
        int lr = lane & 15, half = lane >> 4;
        #pragma unroll
        for (int ntp = 0; ntp < 4; ntp++) {
            int nb = wn * 8 + ntp * 2 + half;
            #pragma unroll
            for (int kt = 0; kt < 2; kt++) {
                int k = kt * 16 + lr;
                b_ld4[ntp][kt] = (uint32_t)(8192 + k * 256 + (((nb ^ (k & 7)) & 15) << 4));
            }
        }
    }

    auto issue = [&](uint32_t sbase) {
        #pragma unroll
        for (int i = 0; i < 4; i++) {
            cp_async16(sb + sbase + dstA[i], srcA[i]);
            srcA[i] += 32;
        }
        #pragma unroll
        for (int i = 0; i < 8; i++) {
            cp_async16(sb + sbase + dstW[i], srcW[i]);
            srcW[i] += 32 * 512;
        }
    };

    issue(0);       CP_COMMIT();
    issue(STG);     CP_COMMIT();

    int cur = 0, nxt2 = 2 * STG;
    for (int it = 0; it < nchunks; ++it) {
        if (it + 1 < nchunks) { CP_WAIT1(); } else { CP_WAIT0(); }
        __syncthreads();
        if (it + 2 < nchunks) {
            issue((uint32_t)nxt2);
            CP_COMMIT();
            nxt2 += STG; if (nxt2 == 3 * STG) nxt2 = 0;
        }
        const uint32_t cbase = (uint32_t)cur;
        cur += STG; if (cur == 3 * STG) cur = 0;

        // ---- load ALL fragments (both kt) up front, then mma stream ----
        uint32_t ah[2][2][4], al[2][2][4];   // [kt][mt]
        uint32_t bh[2][16], bl[2][16];       // [kt][nt*2+j]
        #pragma unroll
        for (int kt = 0; kt < 2; kt++) {
            #pragma unroll
            for (int mt = 0; mt < 2; mt++) {
                ldsm_x4(ah[kt][mt], sb + cbase + a_ld[mt][kt]);
                ldsm_x4(al[kt][mt], sb + cbase + a_ld[mt][kt] + 4096);
            }
            #pragma unroll
            for (int ntp = 0; ntp < 4; ntp++) {
                ldsm_x4_trans(&bh[kt][ntp * 4], sb + cbase + b_ld4[ntp][kt]);
                ldsm_x4_trans(&bl[kt][ntp * 4], sb + cbase + b_ld4[ntp][kt] + 8192);
            }
        }
        #pragma unroll
        for (int kt = 0; kt < 2; kt++)
            #pragma unroll
            for (int mt = 0; mt < 2; mt++)
                #pragma unroll
                for (int nt = 0; nt < 8; nt++) {
                    mma_bf16(acc[mt][nt], ah[kt][mt], &bh[kt][nt * 2]);
                    mma_bf16(acc[mt][nt], ah[kt][mt], &bl[kt][nt * 2]);
                    mma_bf16(acc[mt][nt], al[kt][mt], &bh[kt][nt * 2]);
                }
    }

    {
        const int g = lane >> 2, t4 = lane & 3;
        #pragma unroll
        for (int mt = 0; mt < 2; mt++) {
            int r0 = m0 + wm * 32 + mt * 16 + g;
            int r1 = r0 + 8;
            #pragma unroll
            for (int nt = 0; nt < 8; nt++) {
                int col = n0 + wn * 64 + nt * 8 + t4 * 2;
                atomicAdd(&g_feats[r0 * 512 + col],     acc[mt][nt][0]);
                atomicAdd(&g_feats[r0 * 512 + col + 1], acc[mt][nt][1]);
                atomicAdd(&g_feats[r1 * 512 + col],     acc[mt][nt][2]);
                atomicAdd(&g_feats[r1 * 512 + col + 1], acc[mt][nt][3]);
            }
        }
    }
}

// ---------------- kernel 3: row norms + consistency ----------------
__global__ void post_kernel() {
    __shared__ float red[32];
    const int i = blockIdx.x;
    const int tid = threadIdx.x;
    const int base = i * 512;
    const int b0 = (i & 63) * 512;
    float sq = 0.0f, dsq = 0.0f;
    for (int f = tid; f < 512; f += 256) {
        float v = g_feats[base + f];
        sq += v * v;
        if (i >= 64) {
            float d = v - g_feats[b0 + f];
            dsq += d * d;
        }
    }
    float tsq = blockReduceSum(sq, red);
    float tdq = blockReduceSum(dsq, red);
    if (tid == 0) {
        g_norms[i] = sqrtf(tsq);
        if (i >= 64) atomicAdd(&g_cons, tdq);
    }
}

// ---------------- kernel 4: contrastive ----------------
__global__ void contr_kernel() {
    __shared__ float fi[512];
    __shared__ float simb[320];
    __shared__ float red[32];
    const int i = blockIdx.x;
    const int tid = threadIdx.x;
    for (int f = tid; f < 512; f += 256) fi[f] = g_feats[i * 512 + f];
    __syncthreads();
    const float inv_i = 1.0f / g_norms[i];
    const int w = tid >> 5, lane = tid & 31;
    for (int j = w; j < 320; j += 8) {
        float s = 0.0f;
        const float* fj = g_feats + j * 512;
        #pragma unroll 4
        for (int e = lane; e < 512; e += 32) s += fi[e] * fj[e];
        #pragma unroll
        for (int o = 16; o; o >>= 1) s += __shfl_down_sync(0xffffffffu, s, o);
        if (lane == 0) simb[j] = s * inv_i / g_norms[j] * 10.0f;
    }
    __syncthreads();
    float mx = -3.4e38f;
    for (int j = tid; j < 320; j += 256) mx = fmaxf(mx, simb[j]);
    mx = blockReduceMax(mx, red);
    float se = 0.0f;
    for (int j = tid; j < 320; j += 256) se += expf(simb[j] - mx);
    se = blockReduceSum(se, red);
    if (tid == 0) {
        float lse = mx + logf(se);
        float c = 0.0f;
        if (i > 0)   c += lse - simb[i - 1];
        if (i < 319) c += lse - simb[i + 1];
        atomicAdd(&g_contr, c);
    }
}

// ---------------- kernel 5: finalize ----------------
__global__ void fin_kernel(float* __restrict__ out) {
    out[0] = g_cons * (1.0f / 131072.0f) + 0.5f * (g_contr * (1.0f / 638.0f));
}

// ---------------- launch ----------------
#define VIEWS_SMEM (32768 + 2 * PLANE3 * 8)   /* 106496 */

extern "C" void kernel_launch(void* const* d_in, const int* in_sizes, int n_in,
                              void* d_out, int out_size) {
    const float* x  = (const float*)d_in[0];
    const float* W  = (const float*)d_in[1];
    const float* b  = (const float*)d_in[2];
    const float* n1 = (const float*)d_in[3];
    const float* n2 = (const float*)d_in[4];
    const int* fs   = (const int*)d_in[5];
    const int* ts   = (const int*)d_in[6];
    (void)in_sizes; (void)n_in; (void)out_size;

    cudaFuncSetAttribute(views_kernel, cudaFuncAttributeMaxDynamicSharedMemorySize, VIEWS_SMEM);
    cudaFuncSetAttribute(gemm_kernel, cudaFuncAttributeMaxDynamicSharedMemorySize, GEMM_SMEM);

    init_kernel<<<640, 256>>>(b);
    views_kernel<<<4608, 512, VIEWS_SMEM>>>(x, W, n1, n2, fs, ts);
    gemm_kernel<<<dim3(4, 5, KSPL), 128, GEMM_SMEM>>>();
    post_kernel<<<320, 256>>>();
    contr_kernel<<<320, 256>>>();
    fin_kernel<<<1, 1>>>((float*)d_out);
}

// round 11
// speedup vs baseline: 1.0844x; 1.0844x over previous
#include <cuda_runtime.h>
#include <cuda_bf16.h>
#include <math.h>
#include <stdint.h>

#define TT 4096
#define KTOT (64*4096)   /* 262144 */
#define FD 512

// ---------------- scratch (static device globals) ----------------
__device__ __nv_bfloat16 g_Ah[(size_t)320 * KTOT];
__device__ __nv_bfloat16 g_Al[(size_t)320 * KTOT];
__device__ __nv_bfloat16 g_Wh[(size_t)KTOT * FD];
__device__ __nv_bfloat16 g_Wl[(size_t)KTOT * FD];
__device__ float g_feats[320 * FD];
__device__ float g_norms[320];
__device__ float g_cons;
__device__ float g_contr;

// ---------------- PTX helpers (baseline ISA only) ----------------
__device__ __forceinline__ uint32_t smem_to_u32(const void* p) {
    uint32_t a;
    asm("{ .reg .u64 t; cvta.to.shared.u64 t, %1; cvt.u32.u64 %0, t; }" : "=r"(a) : "l"(p));
    return a;
}
__device__ __forceinline__ void ldsm_x4(uint32_t* r, uint32_t addr) {
    asm volatile("ldmatrix.sync.aligned.m8n8.x4.shared.b16 {%0,%1,%2,%3}, [%4];"
        : "=r"(r[0]), "=r"(r[1]), "=r"(r[2]), "=r"(r[3]) : "r"(addr));
}
__device__ __forceinline__ void ldsm_x4_trans(uint32_t* r, uint32_t addr) {
    asm volatile("ldmatrix.sync.aligned.m8n8.x4.trans.shared.b16 {%0,%1,%2,%3}, [%4];"
        : "=r"(r[0]), "=r"(r[1]), "=r"(r[2]), "=r"(r[3]) : "r"(addr));
}
__device__ __forceinline__ void mma_bf16(float* c, const uint32_t* a, const uint32_t* b) {
    asm volatile("mma.sync.aligned.m16n8k16.row.col.f32.bf16.bf16.f32 "
        "{%0,%1,%2,%3}, {%4,%5,%6,%7}, {%8,%9}, {%0,%1,%2,%3};"
        : "+f"(c[0]), "+f"(c[1]), "+f"(c[2]), "+f"(c[3])
        : "r"(a[0]), "r"(a[1]), "r"(a[2]), "r"(a[3]), "r"(b[0]), "r"(b[1]));
}
__device__ __forceinline__ void cp_async16(uint32_t smem, const void* g) {
    asm volatile("cp.async.cg.shared.global [%0], [%1], 16;" :: "r"(smem), "l"(g));
}
#define CP_COMMIT() asm volatile("cp.async.commit_group;" ::: "memory")
#define CP_WAIT1()  asm volatile("cp.async.wait_group 1;" ::: "memory")
#define CP_WAIT0()  asm volatile("cp.async.wait_group 0;" ::: "memory")

// ---------------- block reductions ----------------
__device__ __forceinline__ float blockReduceSum(float v, float* red) {
    int lane = threadIdx.x & 31, w = threadIdx.x >> 5;
    int nw = blockDim.x >> 5;
    #pragma unroll
    for (int o = 16; o; o >>= 1) v += __shfl_down_sync(0xffffffffu, v, o);
    if (lane == 0) red[w] = v;
    __syncthreads();
    if (w == 0) {
        float r = (lane < nw) ? red[lane] : 0.0f;
        #pragma unroll
        for (int o = 8; o; o >>= 1) r += __shfl_down_sync(0xffffffffu, r, o);
        if (lane == 0) red[0] = r;
    }
    __syncthreads();
    float out = red[0];
    __syncthreads();
    return out;
}
__device__ __forceinline__ float blockReduceMax(float v, float* red) {
    int lane = threadIdx.x & 31, w = threadIdx.x >> 5;
    int nw = blockDim.x >> 5;
    #pragma unroll
    for (int o = 16; o; o >>= 1) v = fmaxf(v, __shfl_down_sync(0xffffffffu, v, o));
    if (lane == 0) red[w] = v;
    __syncthreads();
    if (w == 0) {
        float r = (lane < nw) ? red[lane] : -3.4e38f;
        #pragma unroll
        for (int o = 8; o; o >>= 1) r = fmaxf(r, __shfl_down_sync(0xffffffffu, r, o));
        if (lane == 0) red[0] = r;
    }
    __syncthreads();
    float out = red[0];
    __syncthreads();
    return out;
}

// ---------------- complex / masks / skew ----------------
__device__ __forceinline__ float2 f2add(float2 a, float2 b) { return make_float2(a.x + b.x, a.y + b.y); }
__device__ __forceinline__ float2 f2sub(float2 a, float2 b) { return make_float2(a.x - b.x, a.y - b.y); }
__device__ __forceinline__ float2 cmul(float2 a, float2 b) {
    return make_float2(a.x*b.x - a.y*b.y, a.x*b.y + a.y*b.x);
}
__device__ __forceinline__ float2 cmulc(float2 a, float2 b) {   // conj(a)*b
    return make_float2(a.x*b.x + a.y*b.y, a.x*b.y - a.y*b.x);
}
// folded mask for compressed view (level 0.5): (keep(k)+keep((N-k)%N))/2
__device__ __forceinline__ float m0fold(int k) {
    return (k == 0) ? 1.0f : ((k == 2048) ? 0.0f : 0.5f);
}
// folded fmask: (fm(k)+fm((4096-k)&4095))/2
__device__ __forceinline__ float fmfold(int k, int fs) {
    float f1 = (k >= fs && k < fs + 409) ? 0.1f : 1.0f;
    int k2 = (4096 - k) & 4095;
    float f2 = (k2 >= fs && k2 < fs + 409) ? 0.1f : 1.0f;
    return 0.5f * (f1 + f2);
}
// combined view mask (level 0.25 real-fold g) * fmask — validated since R1 (takes .x)
__device__ __forceinline__ float mask2(int k, int fs) {
    float fm = (k >= fs && k < fs + 409) ? 0.1f : 1.0f;
    float g = (k == 0) ? 1.0f : ((k <= 1024) ? 0.5f : ((k < 3072) ? 1.0f : 0.5f));
    return g * fm;
}
__device__ __forceinline__ int skw3(int g) { return g + (g >> 3); }
#define PLANE3 4608   /* float2 slots per skewed 4096-plane */

// ---------------- radix-8 butterfly ----------------
template<int FWD>
__device__ __forceinline__ void dft8(const float2* e, float2* y) {
    float2 a02s = f2add(e[0], e[4]), a02d = f2sub(e[0], e[4]);
    float2 a13s = f2add(e[2], e[6]), a13d = f2sub(e[2], e[6]);
    float2 A0 = f2add(a02s, a13s), A2 = f2sub(a02s, a13s);
    float2 A1, A3;
    if (FWD) {
        A1 = make_float2(a02d.x + a13d.y, a02d.y - a13d.x);
        A3 = make_float2(a02d.x - a13d.y, a02d.y + a13d.x);
    } else {
        A1 = make_float2(a02d.x - a13d.y, a02d.y + a13d.x);
        A3 = make_float2(a02d.x + a13d.y, a02d.y - a13d.x);
    }
    float2 b02s = f2add(e[1], e[5]), b02d = f2sub(e[1], e[5]);
    float2 b13s = f2add(e[3], e[7]), b13d = f2sub(e[3], e[7]);
    float2 B0 = f2add(b02s, b13s), B2 = f2sub(b02s, b13s);
    float2 B1, B3;
    if (FWD) {
        B1 = make_float2(b02d.x + b13d.y, b02d.y - b13d.x);
        B3 = make_float2(b02d.x - b13d.y, b02d.y + b13d.x);
    } else {
        B1 = make_float2(b02d.x - b13d.y, b02d.y + b13d.x);
        B3 = make_float2(b02d.x + b13d.y, b02d.y - b13d.x);
    }
    const float c = 0.7071067811865476f;
    float2 w1, w2, w3;
    if (FWD) {
        w1 = make_float2(c * (B1.x + B1.y), c * (B1.y - B1.x));
        w2 = make_float2(B2.y, -B2.x);
        w3 = make_float2(c * (B3.y - B3.x), -c * (B3.x + B3.y));
    } else {
        w1 = make_float2(c * (B1.x - B1.y), c * (B1.y + B1.x));
        w2 = make_float2(-B2.y, B2.x);
        w3 = make_float2(-c * (B3.x + B3.y), c * (B3.x - B3.y));
    }
    y[0] = f2add(A0, B0); y[4] = f2sub(A0, B0);
    y[1] = f2add(A1, w1); y[5] = f2sub(A1, w1);
    y[2] = f2add(A2, w2); y[6] = f2sub(A2, w2);
    y[3] = f2add(A3, w3); y[7] = f2sub(A3, w3);
}

// 3 radix-8 smem stages (m = 8, 64, 512). src B0; result in B1.
template<int FWD>
__device__ float2* r8_stages(const float2* __restrict__ tw, float2* B0, float2* B1, int tid) {
    float2 *src = B0, *dst = B1;
    #pragma unroll 1
    for (int s3 = 3; s3 <= 9; s3 += 3) {
        const int m = 1 << s3;
        __syncthreads();
        const int jm = (tid >> s3) << s3;
        float2 e[8], y[8];
        #pragma unroll
        for (int q = 0; q < 8; q++) e[q] = src[skw3(tid + 512 * q)];
        dft8<FWD>(e, y);
        const int base = tid + 7 * jm;
        dst[skw3(base)] = y[0];
        #pragma unroll
        for (int p = 1; p < 8; p++) {
            float2 w = tw[p * jm];
            dst[skw3(base + p * m)] = FWD ? cmul(w, y[p]) : cmulc(w, y[p]);
        }
        float2* t = src; src = dst; dst = t;
    }
    __syncthreads();
    return src;   // == B1
}

// generic inverse pass from register spectrum e[] (already masked/packed)
__device__ float2* inv_core(const float2* __restrict__ tw, float2* e,
                            float2* B0, float2* B1, int tid) {
    float2 y[8];
    dft8<0>(e, y);
    const int base = 8 * tid;
    B0[skw3(base)] = y[0];
    #pragma unroll
    for (int p = 1; p < 8; p++)
        B0[skw3(base + p)] = cmulc(tw[p * tid], y[p]);
    return r8_stages<0>(tw, B0, B1, tid);
}

// ---------------- kernel 0: init ----------------
__global__ void init_kernel(const float* __restrict__ b) {
    int i = blockIdx.x * blockDim.x + threadIdx.x;
    if (i < 320 * FD) g_feats[i] = b[i & 511];
    if (i == 0) { g_cons = 0.0f; g_contr = 0.0f; }
}

// ---------------- views helpers ----------------
__device__ __forceinline__ void store_hl8(size_t idx, const float* v) {
    __align__(16) __nv_bfloat16 hi[8], lo[8];
    #pragma unroll
    for (int q = 0; q < 8; q++) {
        __nv_bfloat16 h = __float2bfloat16_rn(v[q]);
        hi[q] = h;
        lo[q] = __float2bfloat16_rn(v[q] - __bfloat162float(h));
    }
    *(float4*)(g_Ah + idx) = *(float4*)hi;
    *(float4*)(g_Al + idx) = *(float4*)lo;
}
__device__ __forceinline__ void ldg8(float* v, const float* g) {
    float4 u0 = *(const float4*)g;
    float4 u1 = *(const float4*)(g + 4);
    v[0] = u0.x; v[1] = u0.y; v[2] = u0.z; v[3] = u0.w;
    v[4] = u1.x; v[5] = u1.y; v[6] = u1.z; v[7] = u1.w;
}

// ---------------- kernel 1: fused views (radix-8 FFT, packed inverse) + W split ----------------
__global__ void __launch_bounds__(512, 2)
views_kernel(const float* __restrict__ x, const float* __restrict__ W,
             const float* __restrict__ nz1, const float* __restrict__ nz2,
             const int* __restrict__ pfs, const int* __restrict__ pts) {
    const int bx = blockIdx.x;
    const int grp = bx / 9, rr9 = bx % 9;
    const int tid = threadIdx.x;

    if (rr9 == 0) {
        // ---- W hi/lo split slice ----
        size_t base = (size_t)grp * 262144 + (size_t)tid * 8;
        #pragma unroll 1
        for (int j = 0; j < 64; j++) {
            size_t i = base + (size_t)j * 4096;
            float vv[8];
            ldg8(vv, W + i);
            __align__(16) __nv_bfloat16 hi[8], lo[8];
            #pragma unroll
            for (int q = 0; q < 8; q++) {
                __nv_bfloat16 h = __float2bfloat16_rn(vv[q]);
                hi[q] = h;
                lo[q] = __float2bfloat16_rn(vv[q] - __bfloat162float(h));
            }
            *(float4*)(g_Wh + i) = *(float4*)hi;
            *(float4*)(g_Wl + i) = *(float4*)lo;
        }
        return;
    }

    extern __shared__ char smraw[];
    float2* tw = (float2*)smraw;                       // 4096 float2 = 32768 B
    float2* B0 = (float2*)(smraw + 32768);             // PLANE3 float2
    float2* B1 = B0 + PLANE3;
    __shared__ float red[32];

    const int row = grp * 8 + (rr9 - 1);               // 0..4095
    const int bi = row >> 6, ci = row & 63;
    const int fs = *pfs, ts = *pts;
    const size_t xbase = (size_t)row * TT;

    const size_t a0 = (size_t)(0*64 + bi) * KTOT + (size_t)ci * TT;
    const size_t a1 = (size_t)(1*64 + bi) * KTOT + (size_t)ci * TT;
    const size_t a2 = (size_t)(2*64 + bi) * KTOT + (size_t)ci * TT;
    const size_t a3 = (size_t)(3*64 + bi) * KTOT + (size_t)ci * TT;
    const size_t a4 = (size_t)(4*64 + bi) * KTOT + (size_t)ci * TT;

    const int tc = 8 * tid;   // contiguous I/O base

    // twiddles
    #pragma unroll
    for (int j = 0; j < 8; j++) {
        int k = tid + 512 * j;
        float s, c;
        sincospif(-(float)k * (1.0f / 2048.0f), &s, &c);
        tw[k] = make_float2(c, s);
    }

    // contiguous x load; view0; std stats; stash into smem for layout change
    float x8[8];
    ldg8(x8, x + xbase + tc);
    store_hl8(a0 + tc, x8);
    float ls = 0.0f, lq = 0.0f;
    #pragma unroll
    for (int j = 0; j < 8; j++) { ls += x8[j]; lq += x8[j] * x8[j]; }
    {
        float* xs = (float*)B0;
        #pragma unroll
        for (int j = 0; j < 8; j++) xs[tc + j] = x8[j];
    }
    float s1 = blockReduceSum(ls, red);    // internal barriers make xs/tw visible
    float q1 = blockReduceSum(lq, red);
    float std1 = sqrtf(fmaxf(0.0f, (q1 - s1 * s1 * (1.0f / 4096.0f)) * (1.0f / 4095.0f)));

    // noisy view (contiguous)
    {
        float n8[8], o8[8];
        ldg8(n8, nz1 + xbase + tc);
        #pragma unroll
        for (int j = 0; j < 8; j++) o8[j] = x8[j] + n8[j] * (0.02f * std1);
        store_hl8(a3 + tc, o8);
    }

    // pick up x in FFT register layout
    float xv[8];
    {
        const float* xs = (const float*)B0;
        #pragma unroll
        for (int j = 0; j < 8; j++) xv[j] = xs[tid + 512 * j];
    }
    __syncthreads();   // strided reads done before stage0 overwrites B0

    // forward stage 0 from registers (real input)
    {
        float2 e[8], y[8];
        #pragma unroll
        for (int q = 0; q < 8; q++) e[q] = make_float2(xv[q], 0.0f);
        dft8<1>(e, y);
        const int base = 8 * tid;
        B0[skw3(base)] = y[0];
        #pragma unroll
        for (int p = 1; p < 8; p++)
            B0[skw3(base + p)] = cmul(tw[p * tid], y[p]);
    }
    float2* Xp = r8_stages<1>(tw, B0, B1, tid);   // X in B1

    float2 Xr[8];
    #pragma unroll
    for (int j = 0; j < 8; j++) Xr[j] = Xp[skw3(tid + 512 * j)];

    // ---- packed pass: compressed (Re) + distorted (Im) in one inverse FFT ----
    {
        __syncthreads();
        float2 e[8];
        #pragma unroll
        for (int q = 0; q < 8; q++) {
            int k = tid + 512 * q;
            float ma = m0fold(k);
            float mb = fmfold(k, fs);
            // (ma + i*mb) * X
            e[q] = make_float2(ma * Xr[q].x - mb * Xr[q].y,
                               ma * Xr[q].y + mb * Xr[q].x);
        }
        float2* r = inv_core(tw, e, B0, B1, tid);
        float oc[8], od[8];
        #pragma unroll
        for (int j = 0; j < 8; j++) {
            int t = tc + j;
            float2 v = r[skw3(t)];
            oc[j] = v.x * (1.0f / 4096.0f);
            float tm = (t >= ts && t < ts + 204) ? 0.1f : 1.0f;
            od[j] = tm * v.y * (1.0f / 4096.0f);
        }
        store_hl8(a1 + tc, oc);
        store_hl8(a2 + tc, od);
    }

    // ---- pass 2: combined (mask2, take real part — validated path) ----
    {
        __syncthreads();
        float2 e[8];
        #pragma unroll
        for (int q = 0; q < 8; q++) {
            float m = mask2(tid + 512 * q, fs);
            e[q] = make_float2(Xr[q].x * m, Xr[q].y * m);
        }
        float2* r = inv_core(tw, e, B0, B1, tid);
        float vv[8];
        float ls2 = 0.0f, lq2 = 0.0f;
        #pragma unroll
        for (int j = 0; j < 8; j++) {
            int t = tc + j;
            float tm = (t >= ts && t < ts + 204) ? 0.1f : 1.0f;
            float v = tm * r[skw3(t)].x * (1.0f / 4096.0f);
            vv[j] = v;
            ls2 += v; lq2 += v * v;
        }
        float s2 = blockReduceSum(ls2, red);
        float q2 = blockReduceSum(lq2, red);
        float std2 = sqrtf(fmaxf(0.0f, (q2 - s2 * s2 * (1.0f / 4096.0f)) * (1.0f / 4095.0f)));
        float n8[8], o8[8];
        ldg8(n8, nz2 + xbase + tc);
        #pragma unroll
        for (int j = 0; j < 8; j++) o8[j] = vv[j] + n8[j] * (0.02f * std2);
        store_hl8(a4 + tc, o8);
    }
}

// ---------------- kernel 2: 3-stage async mma.sync bf16-split GEMM (R9-proven config) ----------------
#define STG 24576
#define GEMM_SMEM (3 * STG)   /* 73728 */

__global__ void __launch_bounds__(128, 3) gemm_kernel() {
    extern __shared__ char smbuf[];
    const uint32_t sb = smem_to_u32(smbuf);

    const int tid = threadIdx.x;
    const int warp = tid >> 5, lane = tid & 31;
    const int m0 = blockIdx.y * 64;
    const int n0 = blockIdx.x * 128;
    const int z = blockIdx.z;
    const int start_chunk = 372 * z + (z < 8 ? z : 8);
    const int nchunks = 372 + (z < 8 ? 1 : 0);

    const int wm = warp >> 1;
    const int wn = warp & 1;

    float acc[2][8][4];
    #pragma unroll
    for (int a = 0; a < 2; a++)
        #pragma unroll
        for (int b = 0; b < 8; b++)
            #pragma unroll
            for (int c = 0; c < 4; c++) acc[a][b][c] = 0.0f;

    const __nv_bfloat16* srcA[4];
    uint32_t dstA[4];
    #pragma unroll
    for (int i = 0; i < 2; i++) {
        int f = tid + 128 * i;
        int m = f >> 2, kc = f & 3;
        uint32_t rel = (uint32_t)(m * 64 + (((kc + (m >> 1)) & 3) << 4));
        size_t src = (size_t)(m0 + m) * KTOT + (size_t)start_chunk * 32 + kc * 8;
        dstA[i] = rel;            srcA[i] = g_Ah + src;
        dstA[i + 2] = rel + 4096; srcA[i + 2] = g_Al + src;
    }
    const __nv_bfloat16* srcW[8];
    uint32_t dstW[8];
    #pragma unroll
    for (int i = 0; i < 4; i++) {
        int f = tid + 128 * i;
        int k = f >> 4, nc = f & 15;
        uint32_t rel = (uint32_t)(8192 + k * 256 + (((nc ^ (k & 7)) & 15) << 4));
        size_t src = ((size_t)start_chunk * 32 + k) * 512 + n0 + nc * 8;
        dstW[i] = rel;            srcW[i] = g_Wh + src;
        dstW[i + 4] = rel + 8192; srcW[i + 4] = g_Wl + src;
    }

    uint32_t a_ld[2][2];
    {
        int tile = lane >> 3, r = lane & 7;
        #pragma unroll
        for (int mt = 0; mt < 2; mt++)
            #pragma unroll
            for (int kt = 0; kt < 2; kt++) {
                int mm = wm * 32 + mt * 16 + (tile & 1) * 8 + r;
                int kb = kt * 2 + (tile >> 1);
                a_ld[mt][kt] = (uint32_t)(mm * 64 + (((kb + (mm >> 1)) & 3) << 4));
            }
    }
    uint32_t b_ld4[4][2];
    {
        int lr = lane & 15, half = lane >> 4;
        #pragma unroll
        for (int ntp = 0; ntp < 4; ntp++) {
            int nb = wn * 8 + ntp * 2 + half;
            #pragma unroll
            for (int kt = 0; kt < 2; kt++) {
                int k = kt * 16 + lr;
                b_ld4[ntp][kt] = (uint32_t)(8192 + k * 256 + (((nb ^ (k & 7)) & 15) << 4));
            }
        }
    }

    auto issue = [&](uint32_t sbase) {
        #pragma unroll
        for (int i = 0; i < 4; i++) {
            cp_async16(sb + sbase + dstA[i], srcA[i]);
            srcA[i] += 32;
        }
        #pragma unroll
        for (int i = 0; i < 8; i++) {
            cp_async16(sb + sbase + dstW[i], srcW[i]);
            srcW[i] += 32 * 512;
        }
    };

    issue(0);       CP_COMMIT();
    issue(STG);     CP_COMMIT();

    int cur = 0, nxt2 = 2 * STG;
    for (int it = 0; it < nchunks; ++it) {
        if (it + 1 < nchunks) { CP_WAIT1(); } else { CP_WAIT0(); }
        __syncthreads();
        if (it + 2 < nchunks) {
            issue((uint32_t)nxt2);
            CP_COMMIT();
            nxt2 += STG; if (nxt2 == 3 * STG) nxt2 = 0;
        }
        const uint32_t cbase = (uint32_t)cur;
        cur += STG; if (cur == 3 * STG) cur = 0;

        #pragma unroll
        for (int kt = 0; kt < 2; kt++) {
            uint32_t ah[2][4], al[2][4];
            #pragma unroll
            for (int mt = 0; mt < 2; mt++) {
                ldsm_x4(ah[mt], sb + cbase + a_ld[mt][kt]);
                ldsm_x4(al[mt], sb + cbase + a_ld[mt][kt] + 4096);
            }
            uint32_t bh[16], bl[16];
            #pragma unroll
            for (int ntp = 0; ntp < 4; ntp++) {
                ldsm_x4_trans(&bh[ntp * 4], sb + cbase + b_ld4[ntp][kt]);
                ldsm_x4_trans(&bl[ntp * 4], sb + cbase + b_ld4[ntp][kt] + 8192);
            }
            #pragma unroll
            for (int mt = 0; mt < 2; mt++)
                #pragma unroll
                for (int nt = 0; nt < 8; nt++) {
                    mma_bf16(acc[mt][nt], ah[mt], &bh[nt * 2]);
                    mma_bf16(acc[mt][nt], ah[mt], &bl[nt * 2]);
                    mma_bf16(acc[mt][nt], al[mt], &bh[nt * 2]);
                }
        }
    }

    {
        const int g = lane >> 2, t4 = lane & 3;
        #pragma unroll
        for (int mt = 0; mt < 2; mt++) {
            int r0 = m0 + wm * 32 + mt * 16 + g;
            int r1 = r0 + 8;
            #pragma unroll
            for (int nt = 0; nt < 8; nt++) {
                int col = n0 + wn * 64 + nt * 8 + t4 * 2;
                atomicAdd(&g_feats[r0 * 512 + col],     acc[mt][nt][0]);
                atomicAdd(&g_feats[r0 * 512 + col + 1], acc[mt][nt][1]);
                atomicAdd(&g_feats[r1 * 512 + col],     acc[mt][nt][2]);
                atomicAdd(&g_feats[r1 * 512 + col + 1], acc[mt][nt][3]);
            }
        }
    }
}

// ---------------- kernel 3: row norms + consistency ----------------
__global__ void post_kernel() {
    __shared__ float red[32];
    const int i = blockIdx.x;
    const int tid = threadIdx.x;
    const int base = i * 512;
    const int b0 = (i & 63) * 512;
    float sq = 0.0f, dsq = 0.0f;
    for (int f = tid; f < 512; f += 256) {
        float v = g_feats[base + f];
        sq += v * v;
        if (i >= 64) {
            float d = v - g_feats[b0 + f];
            dsq += d * d;
        }
    }
    float tsq = blockReduceSum(sq, red);
    float tdq = blockReduceSum(dsq, red);
    if (tid == 0) {
        g_norms[i] = sqrtf(tsq);
        if (i >= 64) atomicAdd(&g_cons, tdq);
    }
}

// ---------------- kernel 4: contrastive ----------------
__global__ void contr_kernel() {
    __shared__ float fi[512];
    __shared__ float simb[320];
    __shared__ float red[32];
    const int i = blockIdx.x;
    const int tid = threadIdx.x;
    for (int f = tid; f < 512; f += 256) fi[f] = g_feats[i * 512 + f];
    __syncthreads();
    const float inv_i = 1.0f / g_norms[i];
    const int w = tid >> 5, lane = tid & 31;
    for (int j = w; j < 320; j += 8) {
        float s = 0.0f;
        const float* fj = g_feats + j * 512;
        #pragma unroll 4
        for (int e = lane; e < 512; e += 32) s += fi[e] * fj[e];
        #pragma unroll
        for (int o = 16; o; o >>= 1) s += __shfl_down_sync(0xffffffffu, s, o);
        if (lane == 0) simb[j] = s * inv_i / g_norms[j] * 10.0f;
    }
    __syncthreads();
    float mx = -3.4e38f;
    for (int j = tid; j < 320; j += 256) mx = fmaxf(mx, simb[j]);
    mx = blockReduceMax(mx, red);
    float se = 0.0f;
    for (int j = tid; j < 320; j += 256) se += expf(simb[j] - mx);
    se = blockReduceSum(se, red);
    if (tid == 0) {
        float lse = mx + logf(se);
        float c = 0.0f;
        if (i > 0)   c += lse - simb[i - 1];
        if (i < 319) c += lse - simb[i + 1];
        atomicAdd(&g_contr, c);
    }
}

// ---------------- kernel 5: finalize ----------------
__global__ void fin_kernel(float* __restrict__ out) {
    out[0] = g_cons * (1.0f / 131072.0f) + 0.5f * (g_contr * (1.0f / 638.0f));
}

// ---------------- launch ----------------
#define VIEWS_SMEM (32768 + 2 * PLANE3 * 8)   /* 106496 */

extern "C" void kernel_launch(void* const* d_in, const int* in_sizes, int n_in,
                              void* d_out, int out_size) {
    const float* x  = (const float*)d_in[0];
    const float* W  = (const float*)d_in[1];
    const float* b  = (const float*)d_in[2];
    const float* n1 = (const float*)d_in[3];
    const float* n2 = (const float*)d_in[4];
    const int* fs   = (const int*)d_in[5];
    const int* ts   = (const int*)d_in[6];
    (void)in_sizes; (void)n_in; (void)out_size;

    cudaFuncSetAttribute(views_kernel, cudaFuncAttributeMaxDynamicSharedMemorySize, VIEWS_SMEM);
    cudaFuncSetAttribute(gemm_kernel, cudaFuncAttributeMaxDynamicSharedMemorySize, GEMM_SMEM);

    init_kernel<<<640, 256>>>(b);
    views_kernel<<<4608, 512, VIEWS_SMEM>>>(x, W, n1, n2, fs, ts);
    gemm_kernel<<<dim3(4, 5, 22), 128, GEMM_SMEM>>>();
    post_kernel<<<320, 256>>>();
    contr_kernel<<<320, 256>>>();
    fin_kernel<<<1, 1>>>((float*)d_out);
}

// round 12
// speedup vs baseline: 1.1269x; 1.0391x over previous
#include <cuda_runtime.h>
#include <cuda_bf16.h>
#include <math.h>
#include <stdint.h>

#define TT 4096
#define KTOT (64*4096)   /* 262144 */
#define FD 512

// ---------------- scratch (static device globals) ----------------
__device__ __nv_bfloat16 g_Ah[(size_t)320 * KTOT];
__device__ __nv_bfloat16 g_Al[(size_t)320 * KTOT];
__device__ __nv_bfloat16 g_Wh[(size_t)KTOT * FD];
__device__ __nv_bfloat16 g_Wl[(size_t)KTOT * FD];
__device__ float g_feats[320 * FD];
__device__ float g_norms[320];
__device__ float g_cons;
__device__ float g_contr;

// ---------------- PTX helpers (baseline ISA only) ----------------
__device__ __forceinline__ uint32_t smem_to_u32(const void* p) {
    uint32_t a;
    asm("{ .reg .u64 t; cvta.to.shared.u64 t, %1; cvt.u32.u64 %0, t; }" : "=r"(a) : "l"(p));
    return a;
}
__device__ __forceinline__ void ldsm_x4(uint32_t* r, uint32_t addr) {
    asm volatile("ldmatrix.sync.aligned.m8n8.x4.shared.b16 {%0,%1,%2,%3}, [%4];"
        : "=r"(r[0]), "=r"(r[1]), "=r"(r[2]), "=r"(r[3]) : "r"(addr));
}
__device__ __forceinline__ void ldsm_x4_trans(uint32_t* r, uint32_t addr) {
    asm volatile("ldmatrix.sync.aligned.m8n8.x4.trans.shared.b16 {%0,%1,%2,%3}, [%4];"
        : "=r"(r[0]), "=r"(r[1]), "=r"(r[2]), "=r"(r[3]) : "r"(addr));
}
__device__ __forceinline__ void mma_bf16(float* c, const uint32_t* a, const uint32_t* b) {
    asm volatile("mma.sync.aligned.m16n8k16.row.col.f32.bf16.bf16.f32 "
        "{%0,%1,%2,%3}, {%4,%5,%6,%7}, {%8,%9}, {%0,%1,%2,%3};"
        : "+f"(c[0]), "+f"(c[1]), "+f"(c[2]), "+f"(c[3])
        : "r"(a[0]), "r"(a[1]), "r"(a[2]), "r"(a[3]), "r"(b[0]), "r"(b[1]));
}
__device__ __forceinline__ void cp_async16(uint32_t smem, const void* g) {
    asm volatile("cp.async.cg.shared.global [%0], [%1], 16;" :: "r"(smem), "l"(g));
}
#define CP_COMMIT() asm volatile("cp.async.commit_group;" ::: "memory")
#define CP_WAIT1()  asm volatile("cp.async.wait_group 1;" ::: "memory")
#define CP_WAIT0()  asm volatile("cp.async.wait_group 0;" ::: "memory")

// ---------------- block reductions ----------------
__device__ __forceinline__ float blockReduceSum(float v, float* red) {
    int lane = threadIdx.x & 31, w = threadIdx.x >> 5;
    int nw = blockDim.x >> 5;
    #pragma unroll
    for (int o = 16; o; o >>= 1) v += __shfl_down_sync(0xffffffffu, v, o);
    if (lane == 0) red[w] = v;
    __syncthreads();
    if (w == 0) {
        float r = (lane < nw) ? red[lane] : 0.0f;
        #pragma unroll
        for (int o = 8; o; o >>= 1) r += __shfl_down_sync(0xffffffffu, r, o);
        if (lane == 0) red[0] = r;
    }
    __syncthreads();
    float out = red[0];
    __syncthreads();
    return out;
}
__device__ __forceinline__ float blockReduceMax(float v, float* red) {
    int lane = threadIdx.x & 31, w = threadIdx.x >> 5;
    int nw = blockDim.x >> 5;
    #pragma unroll
    for (int o = 16; o; o >>= 1) v = fmaxf(v, __shfl_down_sync(0xffffffffu, v, o));
    if (lane == 0) red[w] = v;
    __syncthreads();
    if (w == 0) {
        float r = (lane < nw) ? red[lane] : -3.4e38f;
        #pragma unroll
        for (int o = 8; o; o >>= 1) r = fmaxf(r, __shfl_down_sync(0xffffffffu, r, o));
        if (lane == 0) red[0] = r;
    }
    __syncthreads();
    float out = red[0];
    __syncthreads();
    return out;
}

// ---------------- complex / masks / skew ----------------
__device__ __forceinline__ float2 f2add(float2 a, float2 b) { return make_float2(a.x + b.x, a.y + b.y); }
__device__ __forceinline__ float2 f2sub(float2 a, float2 b) { return make_float2(a.x - b.x, a.y - b.y); }
__device__ __forceinline__ float2 cmul(float2 a, float2 b) {
    return make_float2(a.x*b.x - a.y*b.y, a.x*b.y + a.y*b.x);
}
__device__ __forceinline__ float2 cmulc(float2 a, float2 b) {   // conj(a)*b
    return make_float2(a.x*b.x + a.y*b.y, a.x*b.y - a.y*b.x);
}
// folded fmask: (fm(k)+fm((4096-k)&4095))/2   (validated: distorted channel since R10)
__device__ __forceinline__ float fmfold(int k, int fs) {
    float f1 = (k >= fs && k < fs + 409) ? 0.1f : 1.0f;
    int k2 = (4096 - k) & 4095;
    float f2 = (k2 >= fs && k2 < fs + 409) ? 0.1f : 1.0f;
    return 0.5f * (f1 + f2);
}
// symmetric g (level 0.25 real-fold) — validated since R1
__device__ __forceinline__ float gmask(int k) {
    return (k == 0) ? 1.0f : ((k <= 1024) ? 0.5f : ((k < 3072) ? 1.0f : 0.5f));
}
__device__ __forceinline__ int skw3(int g) { return g + (g >> 3); }
#define PLANE3 4608   /* float2 slots per skewed 4096-plane */

// ---------------- radix-8 butterfly ----------------
template<int FWD>
__device__ __forceinline__ void dft8(const float2* e, float2* y) {
    float2 a02s = f2add(e[0], e[4]), a02d = f2sub(e[0], e[4]);
    float2 a13s = f2add(e[2], e[6]), a13d = f2sub(e[2], e[6]);
    float2 A0 = f2add(a02s, a13s), A2 = f2sub(a02s, a13s);
    float2 A1, A3;
    if (FWD) {
        A1 = make_float2(a02d.x + a13d.y, a02d.y - a13d.x);
        A3 = make_float2(a02d.x - a13d.y, a02d.y + a13d.x);
    } else {
        A1 = make_float2(a02d.x - a13d.y, a02d.y + a13d.x);
        A3 = make_float2(a02d.x + a13d.y, a02d.y - a13d.x);
    }
    float2 b02s = f2add(e[1], e[5]), b02d = f2sub(e[1], e[5]);
    float2 b13s = f2add(e[3], e[7]), b13d = f2sub(e[3], e[7]);
    float2 B0 = f2add(b02s, b13s), B2 = f2sub(b02s, b13s);
    float2 B1, B3;
    if (FWD) {
        B1 = make_float2(b02d.x + b13d.y, b02d.y - b13d.x);
        B3 = make_float2(b02d.x - b13d.y, b02d.y + b13d.x);
    } else {
        B1 = make_float2(b02d.x - b13d.y, b02d.y + b13d.x);
        B3 = make_float2(b02d.x + b13d.y, b02d.y - b13d.x);
    }
    const float c = 0.7071067811865476f;
    float2 w1, w2, w3;
    if (FWD) {
        w1 = make_float2(c * (B1.x + B1.y), c * (B1.y - B1.x));
        w2 = make_float2(B2.y, -B2.x);
        w3 = make_float2(c * (B3.y - B3.x), -c * (B3.x + B3.y));
    } else {
        w1 = make_float2(c * (B1.x - B1.y), c * (B1.y + B1.x));
        w2 = make_float2(-B2.y, B2.x);
        w3 = make_float2(-c * (B3.x + B3.y), c * (B3.x - B3.y));
    }
    y[0] = f2add(A0, B0); y[4] = f2sub(A0, B0);
    y[1] = f2add(A1, w1); y[5] = f2sub(A1, w1);
    y[2] = f2add(A2, w2); y[6] = f2sub(A2, w2);
    y[3] = f2add(A3, w3); y[7] = f2sub(A3, w3);
}

// 3 radix-8 smem stages (m = 8, 64, 512). src B0; result in B1.
template<int FWD>
__device__ float2* r8_stages(const float2* __restrict__ tw, float2* B0, float2* B1, int tid) {
    float2 *src = B0, *dst = B1;
    #pragma unroll 1
    for (int s3 = 3; s3 <= 9; s3 += 3) {
        const int m = 1 << s3;
        __syncthreads();
        const int jm = (tid >> s3) << s3;
        float2 e[8], y[8];
        #pragma unroll
        for (int q = 0; q < 8; q++) e[q] = src[skw3(tid + 512 * q)];
        dft8<FWD>(e, y);
        const int base = tid + 7 * jm;
        dst[skw3(base)] = y[0];
        #pragma unroll
        for (int p = 1; p < 8; p++) {
            float2 w = tw[p * jm];
            dst[skw3(base + p * m)] = FWD ? cmul(w, y[p]) : cmulc(w, y[p]);
        }
        float2* t = src; src = dst; dst = t;
    }
    __syncthreads();
    return src;   // == B1
}

// generic inverse pass from register spectrum e[] (already masked/packed)
__device__ float2* inv_core(const float2* __restrict__ tw, float2* e,
                            float2* B0, float2* B1, int tid) {
    float2 y[8];
    dft8<0>(e, y);
    const int base = 8 * tid;
    B0[skw3(base)] = y[0];
    #pragma unroll
    for (int p = 1; p < 8; p++)
        B0[skw3(base + p)] = cmulc(tw[p * tid], y[p]);
    return r8_stages<0>(tw, B0, B1, tid);
}

// ---------------- kernel 0: init ----------------
__global__ void init_kernel(const float* __restrict__ b) {
    int i = blockIdx.x * blockDim.x + threadIdx.x;
    if (i < 320 * FD) g_feats[i] = b[i & 511];
    if (i == 0) { g_cons = 0.0f; g_contr = 0.0f; }
}

// ---------------- views helpers ----------------
__device__ __forceinline__ void store_hl8(size_t idx, const float* v) {
    __align__(16) __nv_bfloat16 hi[8], lo[8];
    #pragma unroll
    for (int q = 0; q < 8; q++) {
        __nv_bfloat16 h = __float2bfloat16_rn(v[q]);
        hi[q] = h;
        lo[q] = __float2bfloat16_rn(v[q] - __bfloat162float(h));
    }
    *(float4*)(g_Ah + idx) = *(float4*)hi;
    *(float4*)(g_Al + idx) = *(float4*)lo;
}
__device__ __forceinline__ void ldg8(float* v, const float* g) {
    float4 u0 = *(const float4*)g;
    float4 u1 = *(const float4*)(g + 4);
    v[0] = u0.x; v[1] = u0.y; v[2] = u0.z; v[3] = u0.w;
    v[4] = u1.x; v[5] = u1.y; v[6] = u1.z; v[7] = u1.w;
}

// ---------------- kernel 1: fused views (1 fwd + 1 packed inv FFT) + W split ----------------
__global__ void __launch_bounds__(512, 2)
views_kernel(const float* __restrict__ x, const float* __restrict__ W,
             const float* __restrict__ nz1, const float* __restrict__ nz2,
             const int* __restrict__ pfs, const int* __restrict__ pts) {
    const int bx = blockIdx.x;
    const int grp = bx / 9, rr9 = bx % 9;
    const int tid = threadIdx.x;

    if (rr9 == 0) {
        // ---- W hi/lo split slice ----
        size_t base = (size_t)grp * 262144 + (size_t)tid * 8;
        #pragma unroll 1
        for (int j = 0; j < 64; j++) {
            size_t i = base + (size_t)j * 4096;
            float vv[8];
            ldg8(vv, W + i);
            __align__(16) __nv_bfloat16 hi[8], lo[8];
            #pragma unroll
            for (int q = 0; q < 8; q++) {
                __nv_bfloat16 h = __float2bfloat16_rn(vv[q]);
                hi[q] = h;
                lo[q] = __float2bfloat16_rn(vv[q] - __bfloat162float(h));
            }
            *(float4*)(g_Wh + i) = *(float4*)hi;
            *(float4*)(g_Wl + i) = *(float4*)lo;
        }
        return;
    }

    extern __shared__ char smraw[];
    float2* tw = (float2*)smraw;                       // 4096 float2 = 32768 B
    float2* B0 = (float2*)(smraw + 32768);             // PLANE3 float2
    float2* B1 = B0 + PLANE3;
    __shared__ float red[32];

    const int row = grp * 8 + (rr9 - 1);               // 0..4095
    const int bi = row >> 6, ci = row & 63;
    const int fs = *pfs, ts = *pts;
    const size_t xbase = (size_t)row * TT;

    const size_t a0 = (size_t)(0*64 + bi) * KTOT + (size_t)ci * TT;
    const size_t a1 = (size_t)(1*64 + bi) * KTOT + (size_t)ci * TT;
    const size_t a2 = (size_t)(2*64 + bi) * KTOT + (size_t)ci * TT;
    const size_t a3 = (size_t)(3*64 + bi) * KTOT + (size_t)ci * TT;
    const size_t a4 = (size_t)(4*64 + bi) * KTOT + (size_t)ci * TT;

    const int tc = 8 * tid;   // contiguous I/O base

    // twiddles
    #pragma unroll
    for (int j = 0; j < 8; j++) {
        int k = tid + 512 * j;
        float s, c;
        sincospif(-(float)k * (1.0f / 2048.0f), &s, &c);
        tw[k] = make_float2(c, s);
    }

    // contiguous x load; view0; stats (sum, sumsq, alternating sum); stash to smem
    float x8[8];
    ldg8(x8, x + xbase + tc);
    store_hl8(a0 + tc, x8);
    float ls = 0.0f, lq = 0.0f, la = 0.0f;
    #pragma unroll
    for (int j = 0; j < 8; j++) {
        ls += x8[j]; lq += x8[j] * x8[j];
        la += (j & 1) ? -x8[j] : x8[j];   // parity of t = 8*tid+j is parity of j
    }
    {
        float* xs = (float*)B0;
        #pragma unroll
        for (int j = 0; j < 8; j++) xs[tc + j] = x8[j];
    }
    float X0 = blockReduceSum(ls, red);    // = X[0]; barriers also publish xs/tw
    float q1 = blockReduceSum(lq, red);
    float X2048 = blockReduceSum(la, red); // = X[2048] (real for real x)
    float std1 = sqrtf(fmaxf(0.0f, (q1 - X0 * X0 * (1.0f / 4096.0f)) * (1.0f / 4095.0f)));

    // noisy view (contiguous)
    {
        float n8[8], o8[8];
        ldg8(n8, nz1 + xbase + tc);
        #pragma unroll
        for (int j = 0; j < 8; j++) o8[j] = x8[j] + n8[j] * (0.02f * std1);
        store_hl8(a3 + tc, o8);
    }

    // ---- compressed view: closed form, NO FFT ----
    // compressed[t] = 0.5*x[t] + (0.5/4096)*(X0 - (-1)^t * X2048)
    {
        const float cA = 0.5f / 4096.0f;
        float o8[8];
        #pragma unroll
        for (int j = 0; j < 8; j++) {
            float sgn = (j & 1) ? -1.0f : 1.0f;
            o8[j] = 0.5f * x8[j] + cA * (X0 - sgn * X2048);
        }
        store_hl8(a1 + tc, o8);
    }

    // pick up x in FFT register layout
    float xv[8];
    {
        const float* xs = (const float*)B0;
        #pragma unroll
        for (int j = 0; j < 8; j++) xv[j] = xs[tid + 512 * j];
    }
    __syncthreads();   // strided reads done before stage0 overwrites B0

    // forward stage 0 from registers (real input)
    {
        float2 e[8], y[8];
        #pragma unroll
        for (int q = 0; q < 8; q++) e[q] = make_float2(xv[q], 0.0f);
        dft8<1>(e, y);
        const int base = 8 * tid;
        B0[skw3(base)] = y[0];
        #pragma unroll
        for (int p = 1; p < 8; p++)
            B0[skw3(base + p)] = cmul(tw[p * tid], y[p]);
    }
    float2* Xp = r8_stages<1>(tw, B0, B1, tid);   // X in B1

    float2 Xr[8];
    #pragma unroll
    for (int j = 0; j < 8; j++) Xr[j] = Xp[skw3(tid + 512 * j)];

    // ---- single packed inverse: distorted (Re) + combined-base (Im) ----
    {
        __syncthreads();
        float2 e[8];
        #pragma unroll
        for (int q = 0; q < 8; q++) {
            int k = tid + 512 * q;
            float ma = fmfold(k, fs);           // distorted fold
            float mb = gmask(k) * ma;           // combined fold = g * fmfold (g symmetric)
            e[q] = make_float2(ma * Xr[q].x - mb * Xr[q].y,
                               ma * Xr[q].y + mb * Xr[q].x);
        }
        float2* r = inv_core(tw, e, B0, B1, tid);

        // distorted view
        float od[8];
        // combined base (pre-noise)
        float vc[8];
        float ls2 = 0.0f, lq2 = 0.0f;
        #pragma unroll
        for (int j = 0; j < 8; j++) {
            int t = tc + j;
            float2 v = r[skw3(t)];
            float tm = (t >= ts && t < ts + 204) ? 0.1f : 1.0f;
            od[j] = tm * v.x * (1.0f / 4096.0f);
            float c = tm * v.y * (1.0f / 4096.0f);
            vc[j] = c;
            ls2 += c; lq2 += c * c;
        }
        store_hl8(a2 + tc, od);

        float s2 = blockReduceSum(ls2, red);
        float q2 = blockReduceSum(lq2, red);
        float std2 = sqrtf(fmaxf(0.0f, (q2 - s2 * s2 * (1.0f / 4096.0f)) * (1.0f / 4095.0f)));
        float n8[8], o8[8];
        ldg8(n8, nz2 + xbase + tc);
        #pragma unroll
        for (int j = 0; j < 8; j++) o8[j] = vc[j] + n8[j] * (0.02f * std2);
        store_hl8(a4 + tc, o8);
    }
}

// ---------------- kernel 2: 3-stage async mma.sync bf16-split GEMM (R11-proven, frozen) ----------------
#define STG 24576
#define GEMM_SMEM (3 * STG)   /* 73728 */

__global__ void __launch_bounds__(128, 3) gemm_kernel() {
    extern __shared__ char smbuf[];
    const uint32_t sb = smem_to_u32(smbuf);

    const int tid = threadIdx.x;
    const int warp = tid >> 5, lane = tid & 31;
    const int m0 = blockIdx.y * 64;
    const int n0 = blockIdx.x * 128;
    const int z = blockIdx.z;
    const int start_chunk = 372 * z + (z < 8 ? z : 8);
    const int nchunks = 372 + (z < 8 ? 1 : 0);

    const int wm = warp >> 1;
    const int wn = warp & 1;

    float acc[2][8][4];
    #pragma unroll
    for (int a = 0; a < 2; a++)
        #pragma unroll
        for (int b = 0; b < 8; b++)
            #pragma unroll
            for (int c = 0; c < 4; c++) acc[a][b][c] = 0.0f;

    const __nv_bfloat16* srcA[4];
    uint32_t dstA[4];
    #pragma unroll
    for (int i = 0; i < 2; i++) {
        int f = tid + 128 * i;
        int m = f >> 2, kc = f & 3;
        uint32_t rel = (uint32_t)(m * 64 + (((kc + (m >> 1)) & 3) << 4));
        size_t src = (size_t)(m0 + m) * KTOT + (size_t)start_chunk * 32 + kc * 8;
        dstA[i] = rel;            srcA[i] = g_Ah + src;
        dstA[i + 2] = rel + 4096; srcA[i + 2] = g_Al + src;
    }
    const __nv_bfloat16* srcW[8];
    uint32_t dstW[8];
    #pragma unroll
    for (int i = 0; i < 4; i++) {
        int f = tid + 128 * i;
        int k = f >> 4, nc = f & 15;
        uint32_t rel = (uint32_t)(8192 + k * 256 + (((nc ^ (k & 7)) & 15) << 4));
        size_t src = ((size_t)start_chunk * 32 + k) * 512 + n0 + nc * 8;
        dstW[i] = rel;            srcW[i] = g_Wh + src;
        dstW[i + 4] = rel + 8192; srcW[i + 4] = g_Wl + src;
    }

    uint32_t a_ld[2][2];
    {
        int tile = lane >> 3, r = lane & 7;
        #pragma unroll
        for (int mt = 0; mt < 2; mt++)
            #pragma unroll
            for (int kt = 0; kt < 2; kt++) {
                int mm = wm * 32 + mt * 16 + (tile & 1) * 8 + r;
                int kb = kt * 2 + (tile >> 1);
                a_ld[mt][kt] = (uint32_t)(mm * 64 + (((kb + (mm >> 1)) & 3) << 4));
            }
    }
    uint32_t b_ld4[4][2];
    {
        int lr = lane & 15, half = lane >> 4;
        #pragma unroll
        for (int ntp = 0; ntp < 4; ntp++) {
            int nb = wn * 8 + ntp * 2 + half;
            #pragma unroll
            for (int kt = 0; kt < 2; kt++) {
                int k = kt * 16 + lr;
                b_ld4[ntp][kt] = (uint32_t)(8192 + k * 256 + (((nb ^ (k & 7)) & 15) << 4));
            }
        }
    }

    auto issue = [&](uint32_t sbase) {
        #pragma unroll
        for (int i = 0; i < 4; i++) {
            cp_async16(sb + sbase + dstA[i], srcA[i]);
            srcA[i] += 32;
        }
        #pragma unroll
        for (int i = 0; i < 8; i++) {
            cp_async16(sb + sbase + dstW[i], srcW[i]);
            srcW[i] += 32 * 512;
        }
    };

    issue(0);       CP_COMMIT();
    issue(STG);     CP_COMMIT();

    int cur = 0, nxt2 = 2 * STG;
    for (int it = 0; it < nchunks; ++it) {
        if (it + 1 < nchunks) { CP_WAIT1(); } else { CP_WAIT0(); }
        __syncthreads();
        if (it + 2 < nchunks) {
            issue((uint32_t)nxt2);
            CP_COMMIT();
            nxt2 += STG; if (nxt2 == 3 * STG) nxt2 = 0;
        }
        const uint32_t cbase = (uint32_t)cur;
        cur += STG; if (cur == 3 * STG) cur = 0;

        #pragma unroll
        for (int kt = 0; kt < 2; kt++) {
            uint32_t ah[2][4], al[2][4];
            #pragma unroll
            for (int mt = 0; mt < 2; mt++) {
                ldsm_x4(ah[mt], sb + cbase + a_ld[mt][kt]);
                ldsm_x4(al[mt], sb + cbase + a_ld[mt][kt] + 4096);
            }
            uint32_t bh[16], bl[16];
            #pragma unroll
            for (int ntp = 0; ntp < 4; ntp++) {
                ldsm_x4_trans(&bh[ntp * 4], sb + cbase + b_ld4[ntp][kt]);
                ldsm_x4_trans(&bl[ntp * 4], sb + cbase + b_ld4[ntp][kt] + 8192);
            }
            #pragma unroll
            for (int mt = 0; mt < 2; mt++)
                #pragma unroll
                for (int nt = 0; nt < 8; nt++) {
                    mma_bf16(acc[mt][nt], ah[mt], &bh[nt * 2]);
                    mma_bf16(acc[mt][nt], ah[mt], &bl[nt * 2]);
                    mma_bf16(acc[mt][nt], al[mt], &bh[nt * 2]);
                }
        }
    }

    {
        const int g = lane >> 2, t4 = lane & 3;
        #pragma unroll
        for (int mt = 0; mt < 2; mt++) {
            int r0 = m0 + wm * 32 + mt * 16 + g;
            int r1 = r0 + 8;
            #pragma unroll
            for (int nt = 0; nt < 8; nt++) {
                int col = n0 + wn * 64 + nt * 8 + t4 * 2;
                atomicAdd(&g_feats[r0 * 512 + col],     acc[mt][nt][0]);
                atomicAdd(&g_feats[r0 * 512 + col + 1], acc[mt][nt][1]);
                atomicAdd(&g_feats[r1 * 512 + col],     acc[mt][nt][2]);
                atomicAdd(&g_feats[r1 * 512 + col + 1], acc[mt][nt][3]);
            }
        }
    }
}

// ---------------- kernel 3: row norms + consistency ----------------
__global__ void post_kernel() {
    __shared__ float red[32];
    const int i = blockIdx.x;
    const int tid = threadIdx.x;
    const int base = i * 512;
    const int b0 = (i & 63) * 512;
    float sq = 0.0f, dsq = 0.0f;
    for (int f = tid; f < 512; f += 256) {
        float v = g_feats[base + f];
        sq += v * v;
        if (i >= 64) {
            float d = v - g_feats[b0 + f];
            dsq += d * d;
        }
    }
    float tsq = blockReduceSum(sq, red);
    float tdq = blockReduceSum(dsq, red);
    if (tid == 0) {
        g_norms[i] = sqrtf(tsq);
        if (i >= 64) atomicAdd(&g_cons, tdq);
    }
}

// ---------------- kernel 4: contrastive ----------------
__global__ void contr_kernel() {
    __shared__ float fi[512];
    __shared__ float simb[320];
    __shared__ float red[32];
    const int i = blockIdx.x;
    const int tid = threadIdx.x;
    for (int f = tid; f < 512; f += 256) fi[f] = g_feats[i * 512 + f];
    __syncthreads();
    const float inv_i = 1.0f / g_norms[i];
    const int w = tid >> 5, lane = tid & 31;
    for (int j = w; j < 320; j += 8) {
        float s = 0.0f;
        const float* fj = g_feats + j * 512;
        #pragma unroll 4
        for (int e = lane; e < 512; e += 32) s += fi[e] * fj[e];
        #pragma unroll
        for (int o = 16; o; o >>= 1) s += __shfl_down_sync(0xffffffffu, s, o);
        if (lane == 0) simb[j] = s * inv_i / g_norms[j] * 10.0f;
    }
    __syncthreads();
    float mx = -3.4e38f;
    for (int j = tid; j < 320; j += 256) mx = fmaxf(mx, simb[j]);
    mx = blockReduceMax(mx, red);
    float se = 0.0f;
    for (int j = tid; j < 320; j += 256) se += expf(simb[j] - mx);
    se = blockReduceSum(se, red);
    if (tid == 0) {
        float lse = mx + logf(se);
        float c = 0.0f;
        if (i > 0)   c += lse - simb[i - 1];
        if (i < 319) c += lse - simb[i + 1];
        atomicAdd(&g_contr, c);
    }
}

// ---------------- kernel 5: finalize ----------------
__global__ void fin_kernel(float* __restrict__ out) {
    out[0] = g_cons * (1.0f / 131072.0f) + 0.5f * (g_contr * (1.0f / 638.0f));
}

// ---------------- launch ----------------
#define VIEWS_SMEM (32768 + 2 * PLANE3 * 8)   /* 106496 */

extern "C" void kernel_launch(void* const* d_in, const int* in_sizes, int n_in,
                              void* d_out, int out_size) {
    const float* x  = (const float*)d_in[0];
    const float* W  = (const float*)d_in[1];
    const float* b  = (const float*)d_in[2];
    const float* n1 = (const float*)d_in[3];
    const float* n2 = (const float*)d_in[4];
    const int* fs   = (const int*)d_in[5];
    const int* ts   = (const int*)d_in[6];
    (void)in_sizes; (void)n_in; (void)out_size;

    cudaFuncSetAttribute(views_kernel, cudaFuncAttributeMaxDynamicSharedMemorySize, VIEWS_SMEM);
    cudaFuncSetAttribute(gemm_kernel, cudaFuncAttributeMaxDynamicSharedMemorySize, GEMM_SMEM);

    init_kernel<<<640, 256>>>(b);
    views_kernel<<<4608, 512, VIEWS_SMEM>>>(x, W, n1, n2, fs, ts);
    gemm_kernel<<<dim3(4, 5, 22), 128, GEMM_SMEM>>>();
    post_kernel<<<320, 256>>>();
    contr_kernel<<<320, 256>>>();
    fin_kernel<<<1, 1>>>((float*)d_out);
}